// round 4
// baseline (speedup 1.0000x reference)
#include <cuda_runtime.h>

#define L_TOT    524288
#define M_TOT    (L_TOT / 4)
#define NBATCH   16
#define TILE     2048
#define NTILES   (L_TOT / TILE)   // 256
#define THREADS  256
#define PH2      616              // float2 per phase

typedef unsigned long long u64;

// combined polyphase filters: C[r][dd], dd = d+64 in [0,128]
__device__ float g_C[4][132];

#define FFMA2(acc, a, b) \
    asm("fma.rn.f32x2 %0, %1, %2, %0;" : "+l"(acc) : "l"(a), "l"(b))

__device__ __forceinline__ int physi(int i) { return (i & 7) * 78 + (i >> 3); }

// ---------------- edge kernel: builds g_C + exact two-stage edges ----------
__global__ void pqmf_edge_kernel(const float* __restrict__ x,
                                 const float* __restrict__ qmf,
                                 float* __restrict__ y) {
    __shared__ float s_q[260];
    __shared__ float s_sub[4][16];
    __shared__ float s_part[128];

    const int side = blockIdx.x;          // 0 = low edge, 1 = high edge
    const int b    = blockIdx.y;
    const float* xb = x + (size_t)b * L_TOT;
    float*       yb = y + (size_t)b * L_TOT;
    const int tid = threadIdx.x;          // 128 threads

    for (int i = tid; i < 260; i += 128) s_q[i] = qmf[i];
    __syncthreads();

    // build combined coefficients (redundant across blocks, identical values;
    // main kernel reads g_C only after this kernel completes — stream order)
    for (int idx = tid; idx < 4 * 129; idx += 128) {
        int r  = idx / 129;
        int dd = idx % 129;
        int t0 = (4 - r) & 3;
        float sum = 0.f;
        for (int t = t0; t <= 64; t += 4) {
            int s = dd - t;
            if (s >= 0 && s <= 64) {
                #pragma unroll
                for (int k = 0; k < 4; k++)
                    sum += s_q[k * 65 + t] * s_q[k * 65 + s];
            }
        }
        g_C[r][dd] = sum;
    }

    const int mbase = side ? (M_TOT - 16) : 0;
    if (tid < 64) {
        int k = tid & 3, j = tid >> 2;
        int m = mbase + j;
        float sub = 0.f;
        int pbase = 4 * m - 32;
        for (int s = 0; s <= 64; s++) {
            int pos = pbase + s;
            if (pos >= 0 && pos < L_TOT)
                sub = fmaf(s_q[k * 65 + s], xb[pos], sub);
        }
        s_sub[k][j] = sub;
    }
    __syncthreads();

    float partial = 0.f;
    {
        int nn = tid >> 2, k = tid & 3;
        int n  = side ? (L_TOT - 32 + nn) : nn;
        int t0 = (4 - (n & 3)) & 3;
        for (int t = t0; t <= 64; t += 4) {
            int m = (n + t - 32) >> 2;
            if (m < 0 || m >= M_TOT) continue;
            partial = fmaf(s_q[k * 65 + t], s_sub[k][m - mbase], partial);
        }
    }
    s_part[tid] = partial;
    __syncthreads();
    if (tid < 32) {
        int n = side ? (L_TOT - 32 + tid) : tid;
        yb[n] = s_part[tid * 4] + s_part[tid * 4 + 1] +
                s_part[tid * 4 + 2] + s_part[tid * 4 + 3];
    }
}

// ---------------- main kernel ------------------------------------------------
// Inner FIR over one phase. All LDS at compile-time immediate offsets;
// coefficient and window loads prefetched one step ahead (load->use >= 10 slots).
template<int A, int STEPS>
__device__ __forceinline__ void fir_phase(const float2* __restrict__ B,
                                          const float2* __restrict__ cb,
                                          u64 acc[8]) {
    u64 w[8];
    #pragma unroll
    for (int j = 0; j < 8; j++)
        w[j] = *reinterpret_cast<const u64*>(
            &B[((A + j) & 7) * 78 + ((A + j) >> 3)]);
    u64 c = *reinterpret_cast<const u64*>(&cb[0]);

    #pragma unroll
    for (int e = 0; e < STEPS; e++) {
        u64 c_n = 0, w_n = 0;
        if (e + 1 < STEPS) {           // compile-time in unrolled loop
            c_n = *reinterpret_cast<const u64*>(&cb[e + 1]);
            w_n = *reinterpret_cast<const u64*>(
                &B[((A + e + 8) & 7) * 78 + ((A + e + 8) >> 3)]);
        }
        #pragma unroll
        for (int j = 0; j < 8; j++) FFMA2(acc[j], c, w[j]);
        #pragma unroll
        for (int j = 0; j < 7; j++) w[j] = w[j + 1];
        w[7] = w_n;
        c = c_n;
    }
}

__global__ __launch_bounds__(THREADS, 4)
void pqmf_main2_kernel(const float* __restrict__ x, float* __restrict__ y) {
    __shared__ float2 s_x2[4][PH2];        // phase-split x (b0,b1); reused for y
    __shared__ float2 s_C2[4][4][33];      // coeffs [r][f][e], duplicated

    const int tile  = blockIdx.x;
    const int tbase = tile * TILE;
    const float* x0 = x + (size_t)(2 * blockIdx.y) * L_TOT;
    const float* x1 = x0 + L_TOT;
    float* y0 = y + (size_t)(2 * blockIdx.y) * L_TOT;
    float* y1 = y0 + L_TOT;

    for (int idx = threadIdx.x; idx < TILE + 128; idx += THREADS) {
        int pos = tbase - 64 + idx;
        float a0 = 0.f, b0 = 0.f;
        if (pos >= 0 && pos < L_TOT) { a0 = x0[pos]; b0 = x1[pos]; }
        s_x2[idx & 3][physi(idx >> 2)] = make_float2(a0, b0);
    }
    for (int idx = threadIdx.x; idx < 4 * 4 * 33; idx += THREADS) {
        int r_  = idx / 132;
        int rem = idx % 132;
        int f_  = rem / 33;
        int e_  = rem % 33;
        int dd  = 4 * e_ + f_;
        float c = (dd <= 128) ? g_C[r_][dd] : 0.f;
        s_C2[r_][f_][e_] = make_float2(c, c);
    }
    __syncthreads();

    const int warp = threadIdx.x >> 5;
    const int lane = threadIdx.x & 31;
    const int r    = warp & 3;                  // residue owned by this warp
    const int tq   = (warp >> 2) * 32 + lane;   // 0..63 per residue

    u64 acc[8];
    #pragma unroll
    for (int j = 0; j < 8; j++) acc[j] = 0ULL;

    // y[r+4q] = sum_dd C[r][dd] * sx[r+4q+dd], dd = 4e+f
    #pragma unroll
    for (int f = 0; f < 4; f++) {
        const int df = r + f;
        const float2* B  = &s_x2[df & 3][tq];
        const float2* cb = s_C2[r][f];
        if (f == 0) {
            fir_phase<0, 33>(B, cb, acc);       // df = r -> A = 0 always
        } else {
            if (df >> 2) fir_phase<1, 32>(B, cb, acc);
            else         fir_phase<0, 32>(B, cb, acc);
        }
    }

    __syncthreads();   // all x reads done: reuse s_x2 as y staging

    #pragma unroll
    for (int j = 0; j < 8; j++)
        *reinterpret_cast<u64*>(&s_x2[r][j * 78 + tq]) = acc[j];
    __syncthreads();

    if (tile > 0 && tile < NTILES - 1) {
        #pragma unroll
        for (int idx = threadIdx.x; idx < TILE; idx += THREADS) {
            float2 v = s_x2[idx & 3][physi(idx >> 2)];
            int n = tbase + idx;
            y0[n] = v.x;
            y1[n] = v.y;
        }
    } else {
        for (int idx = threadIdx.x; idx < TILE; idx += THREADS) {
            int n = tbase + idx;
            float2 v = s_x2[idx & 3][physi(idx >> 2)];
            if (n >= 32 && n < L_TOT - 32) {   // edges written by edge kernel
                y0[n] = v.x;
                y1[n] = v.y;
            }
        }
    }
}

extern "C" void kernel_launch(void* const* d_in, const int* in_sizes, int n_in,
                              void* d_out, int out_size) {
    const float* x   = (const float*)d_in[0];
    const float* qmf = (const float*)d_in[1];
    if (n_in >= 2 && in_sizes[0] == 260) {
        x   = (const float*)d_in[1];
        qmf = (const float*)d_in[0];
    }
    float* y = (float*)d_out;

    pqmf_edge_kernel<<<dim3(2, NBATCH), 128>>>(x, qmf, y);
    dim3 grid(NTILES, NBATCH / 2);
    pqmf_main2_kernel<<<grid, THREADS>>>(x, y);
}

// round 5
// speedup vs baseline: 1.0656x; 1.0656x over previous
#include <cuda_runtime.h>

#define L_TOT    524288
#define M_TOT    (L_TOT / 4)
#define NBATCH   16
#define TILE     2048
#define NTILES   (L_TOT / TILE)   // 256
#define THREADS  256
#define PH2      616              // float2 per phase

typedef unsigned long long u64;

// combined polyphase filters: C[r][dd], dd = d+64 in [0,128]
__device__ float g_C[4][132];

#define FFMA2(acc, a, b) \
    asm("fma.rn.f32x2 %0, %1, %2, %0;" : "+l"(acc) : "l"(a), "l"(b))

__device__ __forceinline__ int physi(int i) { return (i & 7) * 78 + (i >> 3); }

// ---------------- edge kernel: builds g_C + exact two-stage edges ----------
__global__ void pqmf_edge_kernel(const float* __restrict__ x,
                                 const float* __restrict__ qmf,
                                 float* __restrict__ y) {
    __shared__ float s_q[260];
    __shared__ float s_sub[4][16];
    __shared__ float s_part[128];

    const int side = blockIdx.x;          // 0 = low edge, 1 = high edge
    const int b    = blockIdx.y;
    const float* xb = x + (size_t)b * L_TOT;
    float*       yb = y + (size_t)b * L_TOT;
    const int tid = threadIdx.x;          // 128 threads

    for (int i = tid; i < 260; i += 128) s_q[i] = qmf[i];
    __syncthreads();

    // build combined coefficients (redundant across blocks, identical values;
    // main kernel reads g_C only after this kernel completes — stream order)
    for (int idx = tid; idx < 4 * 129; idx += 128) {
        int r  = idx / 129;
        int dd = idx % 129;
        int t0 = (4 - r) & 3;
        float sum = 0.f;
        for (int t = t0; t <= 64; t += 4) {
            int s = dd - t;
            if (s >= 0 && s <= 64) {
                #pragma unroll
                for (int k = 0; k < 4; k++)
                    sum += s_q[k * 65 + t] * s_q[k * 65 + s];
            }
        }
        g_C[r][dd] = sum;
    }

    const int mbase = side ? (M_TOT - 16) : 0;
    if (tid < 64) {
        int k = tid & 3, j = tid >> 2;
        int m = mbase + j;
        float sub = 0.f;
        int pbase = 4 * m - 32;
        for (int s = 0; s <= 64; s++) {
            int pos = pbase + s;
            if (pos >= 0 && pos < L_TOT)
                sub = fmaf(s_q[k * 65 + s], xb[pos], sub);
        }
        s_sub[k][j] = sub;
    }
    __syncthreads();

    float partial = 0.f;
    {
        int nn = tid >> 2, k = tid & 3;
        int n  = side ? (L_TOT - 32 + nn) : nn;
        int t0 = (4 - (n & 3)) & 3;
        for (int t = t0; t <= 64; t += 4) {
            int m = (n + t - 32) >> 2;
            if (m < 0 || m >= M_TOT) continue;
            partial = fmaf(s_q[k * 65 + t], s_sub[k][m - mbase], partial);
        }
    }
    s_part[tid] = partial;
    __syncthreads();
    if (tid < 32) {
        int n = side ? (L_TOT - 32 + tid) : tid;
        yb[n] = s_part[tid * 4] + s_part[tid * 4 + 1] +
                s_part[tid * 4 + 2] + s_part[tid * 4 + 3];
    }
}

// ---------------- main kernel ------------------------------------------------
// Inner FIR over one phase. All LDS at compile-time immediate offsets.
// Coefficient (feeds FIRST fma of the chain) prefetched TWO steps ahead;
// window element (feeds LAST fma) prefetched one step ahead.
template<int A, int STEPS>
__device__ __forceinline__ void fir_phase(const float2* __restrict__ B,
                                          const float2* __restrict__ cb,
                                          u64 acc[8]) {
    u64 w[8];
    #pragma unroll
    for (int j = 0; j < 8; j++)
        w[j] = *reinterpret_cast<const u64*>(
            &B[((A + j) & 7) * 78 + ((A + j) >> 3)]);
    u64 c0 = *reinterpret_cast<const u64*>(&cb[0]);
    u64 c1 = (STEPS > 1) ? *reinterpret_cast<const u64*>(&cb[1]) : 0;

    #pragma unroll
    for (int e = 0; e < STEPS; e++) {
        u64 c2 = 0, w_n = 0;
        if (e + 2 < STEPS)              // compile-time in unrolled loop
            c2 = *reinterpret_cast<const u64*>(&cb[e + 2]);
        if (e + 1 < STEPS)
            w_n = *reinterpret_cast<const u64*>(
                &B[((A + e + 8) & 7) * 78 + ((A + e + 8) >> 3)]);
        #pragma unroll
        for (int j = 0; j < 8; j++) FFMA2(acc[j], c0, w[j]);
        #pragma unroll
        for (int j = 0; j < 7; j++) w[j] = w[j + 1];
        w[7] = w_n;
        c0 = c1;
        c1 = c2;
    }
}

__global__ __launch_bounds__(THREADS, 4)
void pqmf_main2_kernel(const float* __restrict__ x, float* __restrict__ y) {
    __shared__ float2 s_x2[4][PH2];        // phase-split x (b0,b1); reused for y
    __shared__ float2 s_C2[4][4][33];      // coeffs [r][f][e], duplicated

    const int tile  = blockIdx.x;
    const int tbase = tile * TILE;
    const float* x0 = x + (size_t)(2 * blockIdx.y) * L_TOT;
    const float* x1 = x0 + L_TOT;
    float* y0 = y + (size_t)(2 * blockIdx.y) * L_TOT;
    float* y1 = y0 + L_TOT;

    for (int idx = threadIdx.x; idx < TILE + 128; idx += THREADS) {
        int pos = tbase - 64 + idx;
        float a0 = 0.f, b0 = 0.f;
        if (pos >= 0 && pos < L_TOT) { a0 = x0[pos]; b0 = x1[pos]; }
        s_x2[idx & 3][physi(idx >> 2)] = make_float2(a0, b0);
    }
    for (int idx = threadIdx.x; idx < 4 * 4 * 33; idx += THREADS) {
        int r_  = idx / 132;
        int rem = idx % 132;
        int f_  = rem / 33;
        int e_  = rem % 33;
        int dd  = 4 * e_ + f_;
        float c = (dd <= 128) ? g_C[r_][dd] : 0.f;
        s_C2[r_][f_][e_] = make_float2(c, c);
    }
    __syncthreads();

    const int warp = threadIdx.x >> 5;
    const int lane = threadIdx.x & 31;
    const int r    = warp & 3;                  // residue owned by this warp
    const int tq   = (warp >> 2) * 32 + lane;   // 0..63 per residue

    u64 acc[8];
    #pragma unroll
    for (int j = 0; j < 8; j++) acc[j] = 0ULL;

    // y[r+4q] = sum_dd C[r][dd] * sx[r+4q+dd], dd = 4e+f
    #pragma unroll
    for (int f = 0; f < 4; f++) {
        const int df = r + f;
        const float2* B  = &s_x2[df & 3][tq];
        const float2* cb = s_C2[r][f];
        if (f == 0) {
            fir_phase<0, 33>(B, cb, acc);       // df = r -> A = 0 always
        } else {
            if (df >> 2) fir_phase<1, 32>(B, cb, acc);
            else         fir_phase<0, 32>(B, cb, acc);
        }
    }

    __syncthreads();   // all x reads done: reuse s_x2 as y staging

    #pragma unroll
    for (int j = 0; j < 8; j++)
        *reinterpret_cast<u64*>(&s_x2[r][j * 78 + tq]) = acc[j];
    __syncthreads();

    if (tile > 0 && tile < NTILES - 1) {
        #pragma unroll
        for (int it = 0; it < TILE / THREADS; it++) {
            int idx = it * THREADS + threadIdx.x;
            float2 v = s_x2[idx & 3][physi(idx >> 2)];
            int n = tbase + idx;
            y0[n] = v.x;
            y1[n] = v.y;
        }
    } else {
        for (int idx = threadIdx.x; idx < TILE; idx += THREADS) {
            int n = tbase + idx;
            float2 v = s_x2[idx & 3][physi(idx >> 2)];
            if (n >= 32 && n < L_TOT - 32) {   // edges written by edge kernel
                y0[n] = v.x;
                y1[n] = v.y;
            }
        }
    }
}

extern "C" void kernel_launch(void* const* d_in, const int* in_sizes, int n_in,
                              void* d_out, int out_size) {
    const float* x   = (const float*)d_in[0];
    const float* qmf = (const float*)d_in[1];
    if (n_in >= 2 && in_sizes[0] == 260) {
        x   = (const float*)d_in[1];
        qmf = (const float*)d_in[0];
    }
    float* y = (float*)d_out;

    pqmf_edge_kernel<<<dim3(2, NBATCH), 128>>>(x, qmf, y);
    dim3 grid(NTILES, NBATCH / 2);
    pqmf_main2_kernel<<<grid, THREADS>>>(x, y);
}